// round 15
// baseline (speedup 1.0000x reference)
#include <cuda_runtime.h>
#include <cstdint>

// Fused blocked online logistic-SGD scan.
// One kernel, 65 clusters x 8 CTAs:
//   cluster 0   : scan (workers wid0-7, prefetch wid8, chain wid9)
//   CTAs 8..519 : band-96 Gram for block m = bid-8, publish release-flag.
// g_WB[m][j][r] pre-scaled by ETA/4: j in [0,32): block m-2, [32,64): m-1,
//   [64,96): intra. Chain corrects dist-1/2 from its own w-history; workers run
//   theta lag-3 with all x loads pre-issued before the c-wait; per-CTA d
//   aggregation (1 remote store+arrive per CTA).
// R15: intra-block recurrence solved by 3 JACOBI SWEEPS over the triangular
//   system h = h0 + L w, w = 1 - tanh(h)  (|L| row sums ~3e-4 => truncation
//   ~(3e-4)^4, exact to fp32). Replaces the 31-step tanh->shfl->fma serial
//   chain (1426 cyc) with ~420 cyc of parallel sweeps.

#define DDIM 2048
#define NSTEPS 16384
#define BLK 32
#define NBLK 512
#define ETA 0.01f
#define NC 8
#define SLICE 256
#define NTH 320
#define BW 96

__device__ float g_WB[(size_t)NBLK * BW * BLK];
__device__ int g_flag[NBLK];   // zero-init; set-once (idempotent across replays)

__device__ __forceinline__ float fast_tanh(float x) {
    float r; asm("tanh.approx.f32 %0, %1;" : "=f"(r) : "f"(x)); return r;
}
__device__ __forceinline__ uint32_t smem_u32(const void* p) {
    return (uint32_t)__cvta_generic_to_shared(p);
}
__device__ __forceinline__ uint32_t mapa_rk(uint32_t a, uint32_t rk) {
    uint32_t r; asm("mapa.shared::cluster.u32 %0, %1, %2;" : "=r"(r) : "r"(a), "r"(rk));
    return r;
}
__device__ __forceinline__ void st_cluster_f32(uint32_t a, float v) {
    asm volatile("st.shared::cluster.f32 [%0], %1;" :: "r"(a), "f"(v) : "memory");
}
__device__ __forceinline__ void cluster_sync_() {
    asm volatile("barrier.cluster.arrive.aligned;" ::: "memory");
    asm volatile("barrier.cluster.wait.aligned;" ::: "memory");
}
__device__ __forceinline__ void mbar_init(uint32_t a, uint32_t cnt) {
    asm volatile("mbarrier.init.shared.b64 [%0], %1;" :: "r"(a), "r"(cnt) : "memory");
}
__device__ __forceinline__ void mbar_arrive_rel(uint32_t a) {
    asm volatile("mbarrier.arrive.release.cluster.shared::cluster.b64 _, [%0];"
                 :: "r"(a) : "memory");
}
__device__ __forceinline__ void mbar_arrive_local(uint32_t a) {
    asm volatile("mbarrier.arrive.shared.b64 _, [%0];" :: "r"(a) : "memory");
}
__device__ __forceinline__ void mbar_wait(uint32_t a, int parity) {
    asm volatile(
        "{\n\t.reg .pred P;\n\t"
        "W_%=:\n\t"
        "mbarrier.try_wait.parity.acquire.cluster.shared::cta.b64 P, [%0], %1, 0x989680;\n\t"
        "@P bra.uni D_%=;\n\t"
        "bra.uni W_%=;\n\t"
        "D_%=:\n\t}"
        :: "r"(a), "r"(parity) : "memory");
}
__device__ __forceinline__ void cp_async16(uint32_t saddr, const void* gptr) {
    asm volatile("cp.async.cg.shared.global [%0], [%1], 16;"
                 :: "r"(saddr), "l"(gptr) : "memory");
}
__device__ __forceinline__ void cp_commit() { asm volatile("cp.async.commit_group;" ::: "memory"); }
__device__ __forceinline__ void cp_wait0()  { asm volatile("cp.async.wait_group 0;" ::: "memory"); }

struct ScanSh {
    float th[SLICE];
    float cbuf[4][BLK];
    float dpart[4][NC][BLK];   // CTA0 only: aggregated per-CTA partials
    float dloc[4][BLK];        // per-CTA local row partials (8 warps x 4 rows)
    float wring[2][BLK];
    alignas(16) float wtmp[BLK];     // Jacobi sweep buffer (CTA0 only)
    unsigned long long mbar_d[4];    // CTA0: NC arrivals (1 per CTA)
    unsigned long long mbar_c[4];    // per CTA: 1 arrival each
    unsigned long long mbar_pf[2];   // prefetch-done
    unsigned long long mbar_cons[2]; // chain-consumed
    alignas(16) float Gsm[2][BW * BLK];
};
struct GramSh { float Bs[96][65]; };
union Sh { ScanSh s; GramSh g; };

__global__ __launch_bounds__(NTH, 1) __cluster_dims__(NC, 1, 1)
void fused_kernel(const float* __restrict__ theta0, const float* __restrict__ xs,
                  float* __restrict__ out) {
    __shared__ Sh u;
    const int tid = threadIdx.x;
    const int bid = blockIdx.x;

    if (bid >= NC) {
        // ================= GRAM role: block m = bid - NC =================
        const int m = bid - NC;
        const int baserow = 32 * m - 64;
        const int r0 = (tid & 7) * 4, j0 = (tid >> 3) * 3;
        const bool act = (tid < 256);
        float acc[4][3];
#pragma unroll
        for (int a = 0; a < 4; a++)
#pragma unroll
            for (int b = 0; b < 3; b++) acc[a][b] = 0.f;

        for (int ch = 0; ch < DDIM / 64; ch++) {
#pragma unroll
            for (int q = 0; q < 5; q++) {
                int id = tid + NTH * q;
                if (id < 1536) {
                    int row = id >> 4, c4 = (id & 15) * 4;
                    int arow = baserow + row;
                    float4 v = make_float4(0.f, 0.f, 0.f, 0.f);
                    if (arow >= 0)
                        v = *(const float4*)(xs + (size_t)arow * DDIM + ch * 64 + c4);
                    u.g.Bs[row][c4+0]=v.x; u.g.Bs[row][c4+1]=v.y;
                    u.g.Bs[row][c4+2]=v.z; u.g.Bs[row][c4+3]=v.w;
                }
            }
            __syncthreads();
            if (act) {
#pragma unroll 8
                for (int d = 0; d < 64; d++) {
                    float a0=u.g.Bs[64+r0+0][d], a1=u.g.Bs[64+r0+1][d];
                    float a2=u.g.Bs[64+r0+2][d], a3=u.g.Bs[64+r0+3][d];
                    float b0=u.g.Bs[j0+0][d], b1=u.g.Bs[j0+1][d], b2=u.g.Bs[j0+2][d];
                    acc[0][0]=fmaf(a0,b0,acc[0][0]); acc[1][0]=fmaf(a1,b0,acc[1][0]);
                    acc[2][0]=fmaf(a2,b0,acc[2][0]); acc[3][0]=fmaf(a3,b0,acc[3][0]);
                    acc[0][1]=fmaf(a0,b1,acc[0][1]); acc[1][1]=fmaf(a1,b1,acc[1][1]);
                    acc[2][1]=fmaf(a2,b1,acc[2][1]); acc[3][1]=fmaf(a3,b1,acc[3][1]);
                    acc[0][2]=fmaf(a0,b2,acc[0][2]); acc[1][2]=fmaf(a1,b2,acc[1][2]);
                    acc[2][2]=fmaf(a2,b2,acc[2][2]); acc[3][2]=fmaf(a3,b2,acc[3][2]);
                }
            }
            __syncthreads();
        }
        if (act) {
            float* dst = g_WB + (size_t)m * (BW * BLK);
#pragma unroll
            for (int rr = 0; rr < 4; rr++)
#pragma unroll
                for (int jj = 0; jj < 3; jj++)
                    dst[(j0 + jj) * BLK + (r0 + rr)] = (0.25f * ETA) * acc[rr][jj];
        }
        __syncthreads();
        if (tid == 0) {
            __threadfence();
            *(volatile int*)&g_flag[m] = 1;
        }
        return;
    }

    // ===================== SCAN role: cluster 0 =====================
    uint32_t rank; asm("mov.u32 %0, %%cluster_ctarank;" : "=r"(rank));
    const int colbase = (int)rank * SLICE;
    const int wid = tid >> 5;
    const int lane = tid & 31;

    if (tid == 0) {
#pragma unroll
        for (int i = 0; i < 4; i++) {
            mbar_init(smem_u32(&u.s.mbar_d[i]), NC);   // 1 arrival per CTA
            mbar_init(smem_u32(&u.s.mbar_c[i]), 1);
        }
#pragma unroll
        for (int i = 0; i < 2; i++) {
            mbar_init(smem_u32(&u.s.mbar_pf[i]), 1);
            mbar_init(smem_u32(&u.s.mbar_cons[i]), 1);
        }
    }
    if (rank == 0 && tid < 64) ((float*)u.s.wring)[tid] = 0.f;
    for (int i = tid; i < SLICE; i += NTH) u.s.th[i] = theta0[colbase + i];
    __syncthreads();
    cluster_sync_();

    if (wid < 8) {
        // ---------------- worker warps 0..7 (all ranks) ----------------
        const int wwarp = wid;
        const int widx = tid;                   // 0..255, owns th[widx]
        const uint32_t dst_base = mapa_rk(smem_u32(&u.s.dpart[0][rank][0]), 0);
        const uint32_t dr_base  = mapa_rk(smem_u32(&u.s.mbar_d[0]), 0);
        const uint32_t mc_base  = smem_u32(&u.s.mbar_c[0]);

        for (int t = 0; t < NBLK; t++) {
            // -- pre-issue ALL x loads for this tick (before any wait) --
            const int uu = t - 3;
            const int uuc = (uu >= 0) ? uu : 0;
            float apv[BLK];
            {
                const float* xp = xs + (size_t)uuc * BLK * DDIM + colbase + widx;
#pragma unroll
                for (int j = 0; j < BLK; j++) apv[j] = xp[(size_t)j * DDIM];
            }
            float4 mva[4], mvb[4];                // matvec x rows (block t)
#pragma unroll
            for (int rr = 0; rr < 4; rr++) {
                const float4* xr = (const float4*)(xs +
                    ((size_t)t * BLK + 4 * wwarp + rr) * DDIM + colbase);
                mva[rr] = xr[lane];
                mvb[rr] = xr[lane + 32];
            }

            if (t >= 3) {
                mbar_wait(mc_base + (uint32_t)(uu & 3) * 8u, (uu >> 2) & 1);
                float tv = u.s.th[widx];
                const float* cp = &u.s.cbuf[uu & 3][0];
#pragma unroll
                for (int j = 0; j < BLK; j++)
                    tv = fmaf(cp[j], apv[j], tv);
                u.s.th[widx] = tv;
            }
            asm volatile("bar.sync 1, 256;" ::: "memory");
            {   // matvec block t with current th (= A_{t-3})
                const float4* th4 = (const float4*)u.s.th;
                float4 t0 = th4[lane], t1 = th4[lane + 32];
                float sacc[4];
#pragma unroll
                for (int rr = 0; rr < 4; rr++) {
                    float4 a = mva[rr], b = mvb[rr];
                    float p0 = a.x * t0.x; p0 = fmaf(a.y, t0.y, p0);
                    p0 = fmaf(a.z, t0.z, p0); p0 = fmaf(a.w, t0.w, p0);
                    float p1 = b.x * t1.x; p1 = fmaf(b.y, t1.y, p1);
                    p1 = fmaf(b.z, t1.z, p1); p1 = fmaf(b.w, t1.w, p1);
                    sacc[rr] = p0 + p1;
                }
#pragma unroll
                for (int rr = 0; rr < 4; rr++) {
                    sacc[rr] += __shfl_xor_sync(0xffffffffu, sacc[rr], 16);
                    sacc[rr] += __shfl_xor_sync(0xffffffffu, sacc[rr], 8);
                    sacc[rr] += __shfl_xor_sync(0xffffffffu, sacc[rr], 4);
                    sacc[rr] += __shfl_xor_sync(0xffffffffu, sacc[rr], 2);
                    sacc[rr] += __shfl_xor_sync(0xffffffffu, sacc[rr], 1);
                }
                // lane 0: store this warp's 4 row-partials to LOCAL smem
                if (lane == 0) {
                    float* dl = &u.s.dloc[t & 3][4 * wwarp];
                    dl[0] = 0.5f * sacc[0];
                    dl[1] = 0.5f * sacc[1];
                    dl[2] = 0.5f * sacc[2];
                    dl[3] = 0.5f * sacc[3];
                }
            }
            asm volatile("bar.sync 1, 256;" ::: "memory");
            // warp 0 aggregates: ONE remote 128B store + ONE arrive per CTA
            if (wwarp == 0) {
                float v = u.s.dloc[t & 3][lane];
                st_cluster_f32(dst_base + (uint32_t)(t & 3) * (NC * BLK * 4)
                               + (uint32_t)lane * 4u, v);
                __syncwarp();
                if (lane == 0)
                    mbar_arrive_rel(dr_base + (uint32_t)(t & 3) * 8u);
            }
        }
        for (int t = NBLK; t < NBLK + 3; t++) {
            int uu = t - 3;
            float apv[BLK];
            const float* xp = xs + (size_t)uu * BLK * DDIM + colbase + widx;
#pragma unroll
            for (int j = 0; j < BLK; j++) apv[j] = xp[(size_t)j * DDIM];
            mbar_wait(mc_base + (uint32_t)(uu & 3) * 8u, (uu >> 2) & 1);
            float tv = u.s.th[widx];
            const float* cp = &u.s.cbuf[uu & 3][0];
#pragma unroll
            for (int j = 0; j < BLK; j++)
                tv = fmaf(cp[j], apv[j], tv);
            u.s.th[widx] = tv;
            asm volatile("bar.sync 1, 256;" ::: "memory");
        }
    } else if (wid == 8) {
        // ---------------- prefetch warp (rank 0 only) ----------------
        if (rank == 0) {
            const int l9 = lane;
            const uint32_t pf_base = smem_u32(&u.s.mbar_pf[0]);
            const uint32_t cons_base = smem_u32(&u.s.mbar_cons[0]);
            for (int s = 0; s < NBLK; s++) {
                if (l9 == 0) {
                    int f;
                    do { asm volatile("ld.acquire.gpu.global.b32 %0, [%1];"
                                      : "=r"(f) : "l"(&g_flag[s]) : "memory"); } while (!f);
                }
                __syncwarp();
                if (s >= 2)
                    mbar_wait(cons_base + (uint32_t)(s & 1) * 8u, ((s - 2) >> 1) & 1);
                const char* gs = (const char*)(g_WB + (size_t)s * BW * BLK);
                uint32_t gd = smem_u32(&u.s.Gsm[s & 1][0]);
#pragma unroll
                for (int i = 0; i < 24; i++)
                    cp_async16(gd + (uint32_t)(l9 + 32 * i) * 16u,
                               gs + (size_t)(l9 + 32 * i) * 16);
                cp_commit();
                cp_wait0();
                __syncwarp();
                if (l9 == 0) mbar_arrive_local(pf_base + (uint32_t)(s & 1) * 8u);
            }
        }
    } else {
        // ---------------- chain warp wid 9 (rank 0 only; hi-wid priority) ----
        if (rank == 0) {
            const uint32_t md_base = smem_u32(&u.s.mbar_d[0]);
            const uint32_t pf_base = smem_u32(&u.s.mbar_pf[0]);
            const uint32_t cons_base = smem_u32(&u.s.mbar_cons[0]);
            const uint32_t cb_base = smem_u32(&u.s.cbuf[0][0]);
            uint32_t cbr[NC - 1];
#pragma unroll
            for (int r = 1; r < NC; r++) cbr[r - 1] = mapa_rk(cb_base, (uint32_t)r);
            const uint32_t rkm = (lane < NC) ? (uint32_t)lane : 0u;
            const uint32_t cr_mine = mapa_rk(smem_u32(&u.s.mbar_c[0]), rkm);

            for (int s = 0; s < NBLK; s++) {
                mbar_wait(pf_base + (uint32_t)(s & 1) * 8u, (s >> 1) & 1);
                const float* Gb = &u.s.Gsm[s & 1][0];
                float Gd2[32], Gd1[32], Gi[32];
#pragma unroll
                for (int j = 0; j < 32; j++) Gd2[j] = Gb[j * 32 + lane];
#pragma unroll
                for (int j = 0; j < 32; j++) Gd1[j] = Gb[(32 + j) * 32 + lane];
                // intra coefficients, strictly-lower-triangular: zero j >= lane
#pragma unroll
                for (int j = 0; j < 32; j++)
                    Gi[j] = (j < lane) ? Gb[(64 + j) * 32 + lane] : 0.f;

                const float4* w2 = (const float4*)&u.s.wring[s & 1][0];
                const float4* w1 = (const float4*)&u.s.wring[(s + 1) & 1][0];
                float a0=0.f, a1=0.f, a2=0.f, a3=0.f;
#pragma unroll
                for (int i = 0; i < 8; i++) {
                    float4 q = w2[i];
                    a0 = fmaf(q.x, Gd2[4*i+0], a0); a1 = fmaf(q.y, Gd2[4*i+1], a1);
                    a2 = fmaf(q.z, Gd2[4*i+2], a2); a3 = fmaf(q.w, Gd2[4*i+3], a3);
                }
#pragma unroll
                for (int i = 0; i < 8; i++) {
                    float4 q = w1[i];
                    a0 = fmaf(q.x, Gd1[4*i+0], a0); a1 = fmaf(q.y, Gd1[4*i+1], a1);
                    a2 = fmaf(q.z, Gd1[4*i+2], a2); a3 = fmaf(q.w, Gd1[4*i+3], a3);
                }
                float corr = (a0 + a1) + (a2 + a3);

                mbar_wait(md_base + (uint32_t)(s & 3) * 8u, (s >> 2) & 1);
                const float* dp = &u.s.dpart[s & 3][0][0];
                float h0 = ((dp[lane] + dp[32 + lane]) + (dp[64 + lane] + dp[96 + lane]))
                         + ((dp[128 + lane] + dp[160 + lane]) + (dp[192 + lane] + dp[224 + lane]))
                         + corr;

                // --- 3 Jacobi sweeps on h = h0 + L w, w = 1 - tanh(h) ---
                float w = 1.0f - fast_tanh(h0);
#pragma unroll
                for (int it = 0; it < 3; it++) {
                    u.s.wtmp[lane] = w;
                    __syncwarp();
                    const float4* wv = (const float4*)u.s.wtmp;
                    float s0 = 0.f, s1 = 0.f, s2 = 0.f, s3 = 0.f;
#pragma unroll
                    for (int i = 0; i < 8; i++) {
                        float4 q = wv[i];
                        s0 = fmaf(q.x, Gi[4*i+0], s0);
                        s1 = fmaf(q.y, Gi[4*i+1], s1);
                        s2 = fmaf(q.z, Gi[4*i+2], s2);
                        s3 = fmaf(q.w, Gi[4*i+3], s3);
                    }
                    float h = h0 + ((s0 + s1) + (s2 + s3));
                    w = 1.0f - fast_tanh(h);
                    __syncwarp();   // order reads before next sweep's write
                }

                u.s.wring[s & 1][lane] = w;
                float c = 0.5f * ETA * w;
                uint32_t coff = (uint32_t)(s & 3) * 128u + (uint32_t)lane * 4u;
                u.s.cbuf[s & 3][lane] = c;
#pragma unroll
                for (int r = 0; r < NC - 1; r++) st_cluster_f32(cbr[r] + coff, c);
                __syncwarp();
                if (lane < NC) mbar_arrive_rel(cr_mine + (uint32_t)(s & 3) * 8u);
                if (lane == 0) mbar_arrive_local(cons_base + (uint32_t)(s & 1) * 8u);
                __syncwarp();
            }
        }
    }

    __syncthreads();
    for (int i = tid; i < SLICE; i += NTH) out[colbase + i] = u.s.th[i];
    cluster_sync_();
}

extern "C" void kernel_launch(void* const* d_in, const int* in_sizes, int n_in,
                              void* d_out, int out_size) {
    const float* theta = (const float*)d_in[0];
    const float* xs    = (const float*)d_in[1];
    if (in_sizes[0] != DDIM) {
        theta = (const float*)d_in[1];
        xs    = (const float*)d_in[0];
    }
    fused_kernel<<<NC + NBLK, NTH>>>(theta, xs, (float*)d_out);
}

// round 17
// speedup vs baseline: 1.2443x; 1.2443x over previous
#include <cuda_runtime.h>
#include <cuda_bf16.h>
#include <cstdint>

// Fused blocked online logistic-SGD scan — double-block chain segments.
// One kernel, 65 clusters x 8 CTAs:
//   cluster 0   : scan (workers wid0-7 [UNCHANGED from R14], prefetch wid8, chain wid9)
//   CTAs 8..519 : band-96 Gram for block m = bid-8 (bf16 output), release-flag.
// g_WB[m][j][r] pre-scaled by ETA/4 (bf16): j in [0,32): block m-2, [32,64): m-1,
//   [64,96): intra.
// R16: chain processes TWO blocks (a=2s, b=2s+1) per segment -> 256 segments
//   instead of 512, halving all per-segment overhead (mbar wakeups, remote
//   visibility, broadcast rounds). b's dist-1 coupling to a is accumulated
//   off-path during a's serial loop (smem bf16 reads); d_b wait overlaps the
//   whole a-solve. G in bf16 smem (4 slots, 24 KB) keeps static smem + regs low.

#define DDIM 2048
#define NSTEPS 16384
#define BLK 32
#define NBLK 512
#define NSEG (NBLK / 2)
#define ETA 0.01f
#define NC 8
#define SLICE 256
#define NTH 320
#define BW 96

__device__ __nv_bfloat16 g_WB[(size_t)NBLK * BW * BLK];
__device__ int g_flag[NBLK];   // zero-init; set-once (idempotent across replays)

__device__ __forceinline__ float fast_tanh(float x) {
    float r; asm("tanh.approx.f32 %0, %1;" : "=f"(r) : "f"(x)); return r;
}
__device__ __forceinline__ uint32_t smem_u32(const void* p) {
    return (uint32_t)__cvta_generic_to_shared(p);
}
__device__ __forceinline__ uint32_t mapa_rk(uint32_t a, uint32_t rk) {
    uint32_t r; asm("mapa.shared::cluster.u32 %0, %1, %2;" : "=r"(r) : "r"(a), "r"(rk));
    return r;
}
__device__ __forceinline__ void st_cluster_f32(uint32_t a, float v) {
    asm volatile("st.shared::cluster.f32 [%0], %1;" :: "r"(a), "f"(v) : "memory");
}
__device__ __forceinline__ void cluster_sync_() {
    asm volatile("barrier.cluster.arrive.aligned;" ::: "memory");
    asm volatile("barrier.cluster.wait.aligned;" ::: "memory");
}
__device__ __forceinline__ void mbar_init(uint32_t a, uint32_t cnt) {
    asm volatile("mbarrier.init.shared.b64 [%0], %1;" :: "r"(a), "r"(cnt) : "memory");
}
__device__ __forceinline__ void mbar_arrive_rel(uint32_t a) {
    asm volatile("mbarrier.arrive.release.cluster.shared::cluster.b64 _, [%0];"
                 :: "r"(a) : "memory");
}
__device__ __forceinline__ void mbar_arrive_local(uint32_t a) {
    asm volatile("mbarrier.arrive.shared.b64 _, [%0];" :: "r"(a) : "memory");
}
__device__ __forceinline__ void mbar_wait(uint32_t a, int parity) {
    asm volatile(
        "{\n\t.reg .pred P;\n\t"
        "W_%=:\n\t"
        "mbarrier.try_wait.parity.acquire.cluster.shared::cta.b64 P, [%0], %1, 0x989680;\n\t"
        "@P bra.uni D_%=;\n\t"
        "bra.uni W_%=;\n\t"
        "D_%=:\n\t}"
        :: "r"(a), "r"(parity) : "memory");
}
__device__ __forceinline__ void cp_async16(uint32_t saddr, const void* gptr) {
    asm volatile("cp.async.cg.shared.global [%0], [%1], 16;"
                 :: "r"(saddr), "l"(gptr) : "memory");
}
__device__ __forceinline__ void cp_commit() { asm volatile("cp.async.commit_group;" ::: "memory"); }
__device__ __forceinline__ void cp_wait0()  { asm volatile("cp.async.wait_group 0;" ::: "memory"); }

__device__ __forceinline__ float b2f(const __nv_bfloat16* p) {
    return __bfloat162float(*p);
}

struct ScanSh {
    float th[SLICE];
    float cbuf[4][BLK];
    float dpart[4][NC][BLK];   // CTA0 only: aggregated per-CTA partials
    float dloc[4][BLK];        // per-CTA local row partials (8 warps x 4 rows)
    float wring[2][BLK];       // [0]: w of last even block, [1]: last odd block
    unsigned long long mbar_d[4];    // CTA0: NC arrivals (1 per CTA), per block
    unsigned long long mbar_c[4];    // per CTA: 1 arrival, per block
    unsigned long long mbar_pf[4];   // per G-slot: prefetch done
    unsigned long long mbar_rel[4];  // per G-slot: chain released
    alignas(16) __nv_bfloat16 Gsm[4][BW * BLK];  // 4 x 6 KB
};
struct GramSh { float Bs[96][65]; };
union Sh { ScanSh s; GramSh g; };

__global__ __launch_bounds__(NTH, 1) __cluster_dims__(NC, 1, 1)
void fused_kernel(const float* __restrict__ theta0, const float* __restrict__ xs,
                  float* __restrict__ out) {
    __shared__ Sh u;
    const int tid = threadIdx.x;
    const int bid = blockIdx.x;

    if (bid >= NC) {
        // ================= GRAM role: block m = bid - NC =================
        const int m = bid - NC;
        const int baserow = 32 * m - 64;
        const int r0 = (tid & 7) * 4, j0 = (tid >> 3) * 3;
        const bool act = (tid < 256);
        float acc[4][3];
#pragma unroll
        for (int a = 0; a < 4; a++)
#pragma unroll
            for (int b = 0; b < 3; b++) acc[a][b] = 0.f;

        for (int ch = 0; ch < DDIM / 64; ch++) {
#pragma unroll
            for (int q = 0; q < 5; q++) {
                int id = tid + NTH * q;
                if (id < 1536) {
                    int row = id >> 4, c4 = (id & 15) * 4;
                    int arow = baserow + row;
                    float4 v = make_float4(0.f, 0.f, 0.f, 0.f);
                    if (arow >= 0)
                        v = *(const float4*)(xs + (size_t)arow * DDIM + ch * 64 + c4);
                    u.g.Bs[row][c4+0]=v.x; u.g.Bs[row][c4+1]=v.y;
                    u.g.Bs[row][c4+2]=v.z; u.g.Bs[row][c4+3]=v.w;
                }
            }
            __syncthreads();
            if (act) {
#pragma unroll 8
                for (int d = 0; d < 64; d++) {
                    float a0=u.g.Bs[64+r0+0][d], a1=u.g.Bs[64+r0+1][d];
                    float a2=u.g.Bs[64+r0+2][d], a3=u.g.Bs[64+r0+3][d];
                    float b0=u.g.Bs[j0+0][d], b1=u.g.Bs[j0+1][d], b2=u.g.Bs[j0+2][d];
                    acc[0][0]=fmaf(a0,b0,acc[0][0]); acc[1][0]=fmaf(a1,b0,acc[1][0]);
                    acc[2][0]=fmaf(a2,b0,acc[2][0]); acc[3][0]=fmaf(a3,b0,acc[3][0]);
                    acc[0][1]=fmaf(a0,b1,acc[0][1]); acc[1][1]=fmaf(a1,b1,acc[1][1]);
                    acc[2][1]=fmaf(a2,b1,acc[2][1]); acc[3][1]=fmaf(a3,b1,acc[3][1]);
                    acc[0][2]=fmaf(a0,b2,acc[0][2]); acc[1][2]=fmaf(a1,b2,acc[1][2]);
                    acc[2][2]=fmaf(a2,b2,acc[2][2]); acc[3][2]=fmaf(a3,b2,acc[3][2]);
                }
            }
            __syncthreads();
        }
        if (act) {
            __nv_bfloat16* dst = g_WB + (size_t)m * (BW * BLK);
#pragma unroll
            for (int rr = 0; rr < 4; rr++)
#pragma unroll
                for (int jj = 0; jj < 3; jj++)
                    dst[(j0 + jj) * BLK + (r0 + rr)] =
                        __float2bfloat16((0.25f * ETA) * acc[rr][jj]);
        }
        __syncthreads();
        if (tid == 0) {
            __threadfence();
            *(volatile int*)&g_flag[m] = 1;
        }
        return;
    }

    // ===================== SCAN role: cluster 0 =====================
    uint32_t rank; asm("mov.u32 %0, %%cluster_ctarank;" : "=r"(rank));
    const int colbase = (int)rank * SLICE;
    const int wid = tid >> 5;
    const int lane = tid & 31;

    if (tid == 0) {
#pragma unroll
        for (int i = 0; i < 4; i++) {
            mbar_init(smem_u32(&u.s.mbar_d[i]), NC);   // 1 arrival per CTA
            mbar_init(smem_u32(&u.s.mbar_c[i]), 1);
            mbar_init(smem_u32(&u.s.mbar_pf[i]), 1);
            mbar_init(smem_u32(&u.s.mbar_rel[i]), 1);
        }
    }
    if (rank == 0 && tid < 64) ((float*)u.s.wring)[tid] = 0.f;
    for (int i = tid; i < SLICE; i += NTH) u.s.th[i] = theta0[colbase + i];
    __syncthreads();
    cluster_sync_();

    if (wid < 8) {
        // ---------------- worker warps 0..7 (all ranks) — UNCHANGED -------
        const int wwarp = wid;
        const int widx = tid;                   // 0..255, owns th[widx]
        const uint32_t dst_base = mapa_rk(smem_u32(&u.s.dpart[0][rank][0]), 0);
        const uint32_t dr_base  = mapa_rk(smem_u32(&u.s.mbar_d[0]), 0);
        const uint32_t mc_base  = smem_u32(&u.s.mbar_c[0]);

        for (int t = 0; t < NBLK; t++) {
            const int uu = t - 3;
            const int uuc = (uu >= 0) ? uu : 0;
            float apv[BLK];
            {
                const float* xp = xs + (size_t)uuc * BLK * DDIM + colbase + widx;
#pragma unroll
                for (int j = 0; j < BLK; j++) apv[j] = xp[(size_t)j * DDIM];
            }
            float4 mva[4], mvb[4];
#pragma unroll
            for (int rr = 0; rr < 4; rr++) {
                const float4* xr = (const float4*)(xs +
                    ((size_t)t * BLK + 4 * wwarp + rr) * DDIM + colbase);
                mva[rr] = xr[lane];
                mvb[rr] = xr[lane + 32];
            }

            if (t >= 3) {
                mbar_wait(mc_base + (uint32_t)(uu & 3) * 8u, (uu >> 2) & 1);
                float tv = u.s.th[widx];
                const float* cp = &u.s.cbuf[uu & 3][0];
#pragma unroll
                for (int j = 0; j < BLK; j++)
                    tv = fmaf(cp[j], apv[j], tv);
                u.s.th[widx] = tv;
            }
            asm volatile("bar.sync 1, 256;" ::: "memory");
            {
                const float4* th4 = (const float4*)u.s.th;
                float4 t0 = th4[lane], t1 = th4[lane + 32];
                float sacc[4];
#pragma unroll
                for (int rr = 0; rr < 4; rr++) {
                    float4 a = mva[rr], b = mvb[rr];
                    float p0 = a.x * t0.x; p0 = fmaf(a.y, t0.y, p0);
                    p0 = fmaf(a.z, t0.z, p0); p0 = fmaf(a.w, t0.w, p0);
                    float p1 = b.x * t1.x; p1 = fmaf(b.y, t1.y, p1);
                    p1 = fmaf(b.z, t1.z, p1); p1 = fmaf(b.w, t1.w, p1);
                    sacc[rr] = p0 + p1;
                }
#pragma unroll
                for (int rr = 0; rr < 4; rr++) {
                    sacc[rr] += __shfl_xor_sync(0xffffffffu, sacc[rr], 16);
                    sacc[rr] += __shfl_xor_sync(0xffffffffu, sacc[rr], 8);
                    sacc[rr] += __shfl_xor_sync(0xffffffffu, sacc[rr], 4);
                    sacc[rr] += __shfl_xor_sync(0xffffffffu, sacc[rr], 2);
                    sacc[rr] += __shfl_xor_sync(0xffffffffu, sacc[rr], 1);
                }
                if (lane == 0) {
                    float* dl = &u.s.dloc[t & 3][4 * wwarp];
                    dl[0] = 0.5f * sacc[0];
                    dl[1] = 0.5f * sacc[1];
                    dl[2] = 0.5f * sacc[2];
                    dl[3] = 0.5f * sacc[3];
                }
            }
            asm volatile("bar.sync 1, 256;" ::: "memory");
            if (wwarp == 0) {
                float v = u.s.dloc[t & 3][lane];
                st_cluster_f32(dst_base + (uint32_t)(t & 3) * (NC * BLK * 4)
                               + (uint32_t)lane * 4u, v);
                __syncwarp();
                if (lane == 0)
                    mbar_arrive_rel(dr_base + (uint32_t)(t & 3) * 8u);
            }
        }
        for (int t = NBLK; t < NBLK + 3; t++) {
            int uu = t - 3;
            float apv[BLK];
            const float* xp = xs + (size_t)uu * BLK * DDIM + colbase + widx;
#pragma unroll
            for (int j = 0; j < BLK; j++) apv[j] = xp[(size_t)j * DDIM];
            mbar_wait(mc_base + (uint32_t)(uu & 3) * 8u, (uu >> 2) & 1);
            float tv = u.s.th[widx];
            const float* cp = &u.s.cbuf[uu & 3][0];
#pragma unroll
            for (int j = 0; j < BLK; j++)
                tv = fmaf(cp[j], apv[j], tv);
            u.s.th[widx] = tv;
            asm volatile("bar.sync 1, 256;" ::: "memory");
        }
    } else if (wid == 8) {
        // ---------------- prefetch warp (rank 0 only): per-block bf16 -----
        if (rank == 0) {
            const uint32_t pf_base  = smem_u32(&u.s.mbar_pf[0]);
            const uint32_t rel_base = smem_u32(&u.s.mbar_rel[0]);
            for (int k = 0; k < NBLK; k++) {
                if (lane == 0) {
                    int f;
                    do { asm volatile("ld.acquire.gpu.global.b32 %0, [%1];"
                                      : "=r"(f) : "l"(&g_flag[k]) : "memory"); } while (!f);
                }
                __syncwarp();
                if (k >= 4)
                    mbar_wait(rel_base + (uint32_t)(k & 3) * 8u, ((k - 4) >> 2) & 1);
                const char* gs = (const char*)(g_WB + (size_t)k * BW * BLK);
                uint32_t gd = smem_u32(&u.s.Gsm[k & 3][0]);
#pragma unroll
                for (int i = 0; i < 12; i++)   // 6144 B = 384 x 16B / 32 lanes
                    cp_async16(gd + (uint32_t)(lane + 32 * i) * 16u,
                               gs + (size_t)(lane + 32 * i) * 16);
                cp_commit();
                cp_wait0();
                __syncwarp();
                if (lane == 0) mbar_arrive_local(pf_base + (uint32_t)(k & 3) * 8u);
            }
        }
    } else {
        // ---------------- chain warp wid 9 (rank 0): double-block segments -
        if (rank == 0) {
            const uint32_t md_base  = smem_u32(&u.s.mbar_d[0]);
            const uint32_t pf_base  = smem_u32(&u.s.mbar_pf[0]);
            const uint32_t rel_base = smem_u32(&u.s.mbar_rel[0]);
            const uint32_t cb_base  = smem_u32(&u.s.cbuf[0][0]);
            uint32_t cbr[NC - 1];
#pragma unroll
            for (int r = 1; r < NC; r++) cbr[r - 1] = mapa_rk(cb_base, (uint32_t)r);
            const uint32_t cr_mine = mapa_rk(smem_u32(&u.s.mbar_c[0]),
                                             (uint32_t)(lane & 7));

            for (int s = 0; s < NSEG; s++) {
                const int a = 2 * s, b = 2 * s + 1;
                mbar_wait(pf_base + (uint32_t)(a & 3) * 8u, (a >> 2) & 1);
                mbar_wait(pf_base + (uint32_t)(b & 3) * 8u, (b >> 2) & 1);
                const __nv_bfloat16* Ga = &u.s.Gsm[a & 3][0];
                const __nv_bfloat16* Gb = &u.s.Gsm[b & 3][0];

                // stage intra coefficients (serial-path) to registers
                float Gia[32], Gib[32];
#pragma unroll
                for (int j = 0; j < 32; j++) Gia[j] = b2f(&Ga[(64 + j) * 32 + lane]);
#pragma unroll
                for (int j = 0; j < 32; j++) Gib[j] = b2f(&Gb[(64 + j) * 32 + lane]);

                // lagged corrections from smem (wring: [0]=w(2s-2), [1]=w(2s-1))
                const float* wE = &u.s.wring[0][0];
                const float* wO = &u.s.wring[1][0];
                float ca0 = 0.f, ca1 = 0.f, cb0 = 0.f, cb1 = 0.f;
#pragma unroll
                for (int j = 0; j < 32; j += 2) {
                    ca0 = fmaf(wE[j],     b2f(&Ga[j * 32 + lane]),        ca0);
                    ca1 = fmaf(wE[j + 1], b2f(&Ga[(j + 1) * 32 + lane]),  ca1);
                    ca0 = fmaf(wO[j],     b2f(&Ga[(32 + j) * 32 + lane]), ca0);
                    ca1 = fmaf(wO[j + 1], b2f(&Ga[(33 + j) * 32 + lane]), ca1);
                    cb0 = fmaf(wO[j],     b2f(&Gb[j * 32 + lane]),        cb0);
                    cb1 = fmaf(wO[j + 1], b2f(&Gb[(j + 1) * 32 + lane]),  cb1);
                }
                float corr_a = ca0 + ca1;
                float corr_b = cb0 + cb1;

                // h_a: needs d(a)
                mbar_wait(md_base + (uint32_t)(a & 3) * 8u, (a >> 2) & 1);
                const float* dpa = &u.s.dpart[a & 3][0][0];
                float h_a = ((dpa[lane] + dpa[32+lane]) + (dpa[64+lane] + dpa[96+lane]))
                          + ((dpa[128+lane] + dpa[160+lane]) + (dpa[192+lane] + dpa[224+lane]))
                          + corr_a;

                // serial solve block a; accumulate b's coupling to a off-path
                float acc_b = 0.f;
                float t = fast_tanh(h_a);
                float myta = 0.f, mytb = 0.f;
#pragma unroll
                for (int r = 1; r < 32; r++) {
                    float tb = __shfl_sync(0xffffffffu, t, r - 1);
                    myta = (lane == r - 1) ? t : myta;
                    float gb1 = b2f(&Gb[(32 + r - 1) * 32 + lane]);   // off-path
                    acc_b = fmaf(tb, -gb1, acc_b + gb1);
                    h_a = fmaf(tb, -Gia[r - 1], h_a + Gia[r - 1]);
                    t = fast_tanh(h_a);
                }
                myta = (lane == 31) ? t : myta;
                {
                    float tb = __shfl_sync(0xffffffffu, t, 31);
                    float gb1 = b2f(&Gb[63 * 32 + lane]);
                    acc_b = fmaf(tb, -gb1, acc_b + gb1);
                }

                // h_b: d(b) wait overlapped the entire a-solve
                mbar_wait(md_base + (uint32_t)(b & 3) * 8u, (b >> 2) & 1);
                const float* dpb = &u.s.dpart[b & 3][0][0];
                float h_b = ((dpb[lane] + dpb[32+lane]) + (dpb[64+lane] + dpb[96+lane]))
                          + ((dpb[128+lane] + dpb[160+lane]) + (dpb[192+lane] + dpb[224+lane]))
                          + corr_b + acc_b;

                float t2 = fast_tanh(h_b);
#pragma unroll
                for (int r = 1; r < 32; r++) {
                    float tb = __shfl_sync(0xffffffffu, t2, r - 1);
                    mytb = (lane == r - 1) ? t2 : mytb;
                    h_b = fmaf(tb, -Gib[r - 1], h_b + Gib[r - 1]);
                    t2 = fast_tanh(h_b);
                }
                mytb = (lane == 31) ? t2 : mytb;

                float w_a = 1.0f - myta;
                float w_b = 1.0f - mytb;
                u.s.wring[0][lane] = w_a;
                u.s.wring[1][lane] = w_b;
                float c_a = 0.5f * ETA * w_a;
                float c_b = 0.5f * ETA * w_b;
                uint32_t coffa = (uint32_t)(a & 3) * 128u + (uint32_t)lane * 4u;
                uint32_t coffb = (uint32_t)(b & 3) * 128u + (uint32_t)lane * 4u;
                u.s.cbuf[a & 3][lane] = c_a;
                u.s.cbuf[b & 3][lane] = c_b;
#pragma unroll
                for (int r = 0; r < NC - 1; r++) {
                    st_cluster_f32(cbr[r] + coffa, c_a);
                    st_cluster_f32(cbr[r] + coffb, c_b);
                }
                __syncwarp();
                if (lane < 8)
                    mbar_arrive_rel(cr_mine + (uint32_t)(a & 3) * 8u);
                else if (lane < 16)
                    mbar_arrive_rel(cr_mine + (uint32_t)(b & 3) * 8u);
                if (lane == 16) mbar_arrive_local(rel_base + (uint32_t)(a & 3) * 8u);
                if (lane == 17) mbar_arrive_local(rel_base + (uint32_t)(b & 3) * 8u);
                __syncwarp();
            }
        }
    }

    __syncthreads();
    for (int i = tid; i < SLICE; i += NTH) out[colbase + i] = u.s.th[i];
    cluster_sync_();
}

extern "C" void kernel_launch(void* const* d_in, const int* in_sizes, int n_in,
                              void* d_out, int out_size) {
    const float* theta = (const float*)d_in[0];
    const float* xs    = (const float*)d_in[1];
    if (in_sizes[0] != DDIM) {
        theta = (const float*)d_in[1];
        xs    = (const float*)d_in[0];
    }
    fused_kernel<<<NC + NBLK, NTH>>>(theta, xs, (float*)d_out);
}